// round 9
// baseline (speedup 1.0000x reference)
#include <cuda_runtime.h>
#include <cuda_bf16.h>
#include <cstdint>
#include <cstddef>

#define NB 8192
#define NC 32000
#define ND 32

static constexpr int TM   = 128;              // rows per CTA
static constexpr int TN   = 128;              // classes per tile
static constexpr int GY   = 50;               // class splits
static constexpr int TPC  = NC / (GY * TN);   // 5 tiles per CTA
static constexpr int CPS  = TPC * TN;         // 640 classes per split
static constexpr int GX   = NB / TM;          // 64 row blocks
static constexpr int RPAD = 80;               // padded row bytes (64 real)
static constexpr int BUFB = TN * RPAD;        // 10240 B per B buffer

#define Y_MIN (1.0f + 1e-6f)

__device__ float g_S[NB];                       // per-row sum of exp(-dist)
__device__ float g_D[NB];                       // per-row target distance
__device__ float g_sumvec[GY * ND];             // per-split class-sum vectors (fp32 of bf16)
__device__ __nv_bfloat16 g_pred_bf[NB * ND];    // sign-folded pred (bf16)
__device__ __nv_bfloat16 g_emb_bf[NC * ND];     // class embeddings (bf16)

// ---------------- helpers -----------------------------------------------------
__device__ __forceinline__ uint32_t smem_u32(const void* p) {
    uint32_t r;
    asm("{ .reg .u64 t; cvta.to.shared.u64 t, %1; cvt.u32.u64 %0, t; }" : "=r"(r) : "l"(p));
    return r;
}
__device__ __forceinline__ void cp16(uint32_t dst, const void* src) {
    asm volatile("cp.async.cg.shared.global [%0], [%1], 16;" :: "r"(dst), "l"(src));
}
__device__ __forceinline__ void ldsm4(uint32_t& r0, uint32_t& r1, uint32_t& r2, uint32_t& r3,
                                      uint32_t a) {
    asm volatile("ldmatrix.sync.aligned.m8n8.x4.shared.b16 {%0,%1,%2,%3}, [%4];"
                 : "=r"(r0), "=r"(r1), "=r"(r2), "=r"(r3) : "r"(a));
}
__device__ __forceinline__ void mma16816(float* c, const uint32_t* a, uint32_t b0, uint32_t b1) {
    asm volatile(
        "mma.sync.aligned.m16n8k16.row.col.f32.bf16.bf16.f32 "
        "{%0,%1,%2,%3}, {%4,%5,%6,%7}, {%8,%9}, {%0,%1,%2,%3};"
        : "+f"(c[0]), "+f"(c[1]), "+f"(c[2]), "+f"(c[3])
        : "r"(a[0]), "r"(a[1]), "r"(a[2]), "r"(a[3]), "r"(b0), "r"(b1));
}
__device__ __forceinline__ float sqrt_approx(float x) {
    float r; asm("sqrt.approx.f32 %0, %1;" : "=f"(r) : "f"(x)); return r;
}
// sqrt(y^2-1) with clamp; Sum(y) is added back separately via g_sumvec
__device__ __forceinline__ float sq_part(float y) {
    y = fmaxf(y, Y_MIN);
    return sqrt_approx(fmaf(y, y, -1.0f));
}

// ---------------- prep kernels (unchanged from the 106.5us version) -----------
__global__ void __launch_bounds__(256) k_prep(const float* __restrict__ pred,
                                              float* __restrict__ out) {
    int i = blockIdx.x * 256 + threadIdx.x;          // grid 512 -> i < 131072
    float2 v = reinterpret_cast<const float2*>(pred)[i];
    int k = (i * 2) & 31;
    float a = (k == 0) ? v.x : -v.x;
    reinterpret_cast<__nv_bfloat162*>(g_pred_bf)[i] = __floats2bfloat162_rn(a, -v.y);
    if (i < NB) g_S[i] = 0.0f;
    if (i == 0) out[0] = 0.0f;
}

__global__ void __launch_bounds__(256) k_cemb(const float* __restrict__ embs) {
    int i = blockIdx.x * 256 + threadIdx.x;          // grid 2000 -> i < 512000
    float2 v = reinterpret_cast<const float2*>(embs)[i];
    reinterpret_cast<__nv_bfloat162*>(g_emb_bf)[i] = __floats2bfloat162_rn(v.x, v.y);
}

// ---------------- k_aux: class-sum vectors + target distances -----------------
// blocks [0,GY): per-split sum vectors from bf16 embs (fp32 accumulate).
// blocks [GY, GY+1024): warp-per-row target distance (independent of g_S).
__global__ void __launch_bounds__(256) k_aux(const float* __restrict__ pred,
                                             const int* __restrict__ tgt,
                                             const float* __restrict__ embs) {
    int b   = blockIdx.x;
    int tid = threadIdx.x;
    if (b < GY) {
        __shared__ float red[8][32];
        int dim = tid & 31;
        int ch  = tid >> 5;                    // 8 chunks of 80 classes
        const __nv_bfloat16* base = g_emb_bf + (size_t)b * CPS * ND;
        float acc = 0.0f;
#pragma unroll 4
        for (int c = ch * 80; c < ch * 80 + 80; c++)
            acc += __bfloat162float(base[c * ND + dim]);
        red[ch][dim] = acc;
        __syncthreads();                       // convergent: all 256 threads
        if (ch == 0) {
            float t = acc;
#pragma unroll
            for (int k = 1; k < 8; k++) t += red[k][dim];
            g_sumvec[b * ND + dim] = t;
        }
    } else {
        // warp-per-row gather: lane = dimension, no barriers in this branch
        int r    = ((b - GY) * 256 + tid) >> 5;     // row 0..8191
        int lane = tid & 31;
        int t = tgt[r];
        float p = pred[r * ND + lane];
        float e = __ldg(&embs[(size_t)t * ND + lane]);
        float term = (lane == 0) ? p * e : -p * e;
#pragma unroll
        for (int o = 16; o; o >>= 1) term += __shfl_xor_sync(0xffffffffu, term, o);
        if (lane == 0) g_D[r] = acoshf(fmaxf(term, Y_MIN));
    }
}

// ---------------- main: mma.sync GEMM + fused sqrt epilogue -------------------
// Loop skeleton identical to the benched 106.5us kernel (2-buffer double buffer,
// leading+trailing sync). Only the epilogue math changed: accumulate sqrt(y^2-1)
// only; Sum(y) recovered per row via the sumvec dot (s_ydot).
__global__ void __launch_bounds__(256) k_main() {
    __shared__ __align__(16) char sA[TM * RPAD];        // 10240 B
    __shared__ __align__(16) char sB[2][TN * RPAD];     // 2 x 10240 B
    __shared__ float s_ydot[TM];

    const int tid  = threadIdx.x;
    const int w    = tid >> 5;
    const int lane = tid & 31;

    const uint32_t a_s = smem_u32(sA);
    const uint32_t b_s = smem_u32(sB);

    const char* gA = reinterpret_cast<const char*>(g_pred_bf) + (size_t)blockIdx.x * TM * 64;
    const int cls_base = blockIdx.y * (TPC * TN);
    const char* gB0 = reinterpret_cast<const char*>(g_emb_bf) + (size_t)cls_base * 64;

    // ---- prologue: stage A and B tile 0 ----
#pragma unroll
    for (int i = 0; i < 2; i++) {
        int L = tid + i * 256;                 // 512 x 16B chunks each
        int r = L >> 2, c = L & 3;
        cp16(a_s + r * RPAD + c * 16, gA + r * 64 + c * 16);
        cp16(b_s + r * RPAD + c * 16, gB0 + r * 64 + c * 16);
    }
    asm volatile("cp.async.commit_group;" ::: "memory");
    asm volatile("cp.async.wait_group 0;" ::: "memory");
    __syncthreads();

    // ---- per-row Sum(y) via sumvec dot (warp-uniform guard, no barrier) ----
    if (tid < TM) {
        const float* sv = g_sumvec + blockIdx.y * ND;
        const __nv_bfloat162* ar = reinterpret_cast<const __nv_bfloat162*>(sA + tid * RPAD);
        float d = 0.0f;
#pragma unroll
        for (int k = 0; k < 16; k++) {
            float2 u = __bfloat1622float2(ar[k]);
            d = fmaf(u.x, sv[2 * k], d);
            d = fmaf(u.y, sv[2 * k + 1], d);
        }
        s_ydot[tid] = d;
    }

    // ---- A fragments (rows w*16 .. w*16+15, K=32) ----
    const int rA = (lane & 7) + ((lane >> 3) & 1) * 8;
    const int cA = (lane >> 4) & 1;
    uint32_t afrag[2][4];
    {
        uint32_t base = a_s + (w * 16 + rA) * RPAD + cA * 16;
        ldsm4(afrag[0][0], afrag[0][1], afrag[0][2], afrag[0][3], base);
        ldsm4(afrag[1][0], afrag[1][1], afrag[1][2], afrag[1][3], base + 32);
    }

    const int rB = (lane & 7) + ((lane >> 4) & 1) * 8;
    const int cB = (lane >> 3) & 1;

    float acc0 = 0.0f, acc1 = 0.0f, acc2 = 0.0f, acc3 = 0.0f;

    int buf = 0;
#pragma unroll 1
    for (int t = 0; t < TPC; t++) {
        if (t + 1 < TPC) {
            const char* gB = reinterpret_cast<const char*>(g_emb_bf)
                           + (size_t)(cls_base + (t + 1) * TN) * 64;
            uint32_t dst = b_s + (buf ^ 1) * BUFB;
#pragma unroll
            for (int i = 0; i < 2; i++) {
                int L = tid + i * 256;
                int r = L >> 2, c = L & 3;
                cp16(dst + r * RPAD + c * 16, gB + r * 64 + c * 16);
            }
            asm volatile("cp.async.commit_group;" ::: "memory");
            asm volatile("cp.async.wait_group 1;" ::: "memory");
        } else {
            asm volatile("cp.async.wait_group 0;" ::: "memory");
        }
        __syncthreads();

        const uint32_t bbase = b_s + buf * BUFB + rB * RPAD + cB * 16;

#pragma unroll
        for (int g = 0; g < TN / 16; g++) {          // 8 groups of 16 classes
            float cL[4] = {0.f, 0.f, 0.f, 0.f};
            float cH[4] = {0.f, 0.f, 0.f, 0.f};
#pragma unroll
            for (int ks = 0; ks < 2; ks++) {
                uint32_t bL0, bL1, bH0, bH1;
                ldsm4(bL0, bL1, bH0, bH1, bbase + g * (16 * RPAD) + ks * 32);
                mma16816(cL, afrag[ks], bL0, bL1);
                mma16816(cH, afrag[ks], bH0, bH1);
            }
            acc0 += sq_part(cL[0]) + sq_part(cL[1]);
            acc1 += sq_part(cH[0]) + sq_part(cH[1]);
            acc2 += sq_part(cL[2]) + sq_part(cL[3]);
            acc3 += sq_part(cH[2]) + sq_part(cH[3]);
        }
        __syncthreads();     // all warps done with buf before it is overwritten
        buf ^= 1;
    }

    // rows: acc0+acc1 -> row lane>>2 ; acc2+acc3 -> row (lane>>2)+8 of warp's 16
    float rlo = acc0 + acc1;
    float rhi = acc2 + acc3;
#pragma unroll
    for (int o = 1; o <= 2; o <<= 1) {
        rlo += __shfl_xor_sync(0xffffffffu, rlo, o);
        rhi += __shfl_xor_sync(0xffffffffu, rhi, o);
    }
    if ((lane & 3) == 0) {
        int rloc = w * 16 + (lane >> 2);
        int rowbase = blockIdx.x * TM + rloc;
        atomicAdd(&g_S[rowbase],     s_ydot[rloc]     - rlo);   // Sum(y - sqrt(y^2-1))
        atomicAdd(&g_S[rowbase + 8], s_ydot[rloc + 8] - rhi);
    }
}

// ---------------- k_log: nll = log(S) + dist_target, mean ---------------------
__global__ void __launch_bounds__(256) k_log(float* __restrict__ out) {
    __shared__ float sm[8];
    int r = blockIdx.x * 256 + threadIdx.x;     // grid 32 -> r < 8192
    float nll = logf(g_S[r]) + g_D[r];
#pragma unroll
    for (int o = 16; o; o >>= 1) nll += __shfl_down_sync(0xffffffffu, nll, o);
    if ((threadIdx.x & 31) == 0) sm[threadIdx.x >> 5] = nll;
    __syncthreads();                            // convergent: all threads
    if (threadIdx.x == 0) {
        float s = 0.0f;
#pragma unroll
        for (int k = 0; k < 8; k++) s += sm[k];
        atomicAdd(out, s * (1.0f / NB));
    }
}

// ---------------- launch ------------------------------------------------------
extern "C" void kernel_launch(void* const* d_in, const int* in_sizes, int n_in,
                              void* d_out, int out_size) {
    const float* pred = (const float*)d_in[0];
    const int*   tgt  = (const int*)  d_in[1];
    const float* embs = (const float*)d_in[2];
    float* out = (float*)d_out;

    k_prep<<<(NB * ND / 2) / 256, 256>>>(pred, out);
    k_cemb<<<(NC * ND / 2) / 256, 256>>>(embs);
    k_aux<<<GY + NB * 32 / 256, 256>>>(pred, tgt, embs);
    k_main<<<dim3(GX, GY), 256>>>();
    k_log<<<NB / 256, 256>>>(out);
}

// round 10
// speedup vs baseline: 1.0647x; 1.0647x over previous
#include <cuda_runtime.h>
#include <cuda_bf16.h>
#include <cstdint>
#include <cstddef>

#define NB 8192
#define NC 32000
#define ND 32

static constexpr int TM   = 128;              // rows per CTA
static constexpr int TN   = 128;              // classes per tile
static constexpr int GY   = 50;               // class splits
static constexpr int TPC  = NC / (GY * TN);   // 5 tiles per CTA
static constexpr int CPS  = TPC * TN;         // 640 classes per split
static constexpr int GX   = NB / TM;          // 64 row blocks
static constexpr int RPAD = 80;               // padded row bytes (64 real)
static constexpr int BUFB = TN * RPAD;        // 10240 B per B buffer

static constexpr int PREB = 512;              // pred-convert blocks in k_pre

#define Y_MIN (1.0f + 1e-6f)

typedef unsigned long long ull;
static constexpr ull NEG1_2 = 0xBF800000BF800000ull;   // (-1.0f, -1.0f) packed

__device__ float g_S[NB];                       // per-row sum of exp(-dist)
__device__ float g_D[NB];                       // per-row target distance
__device__ float g_sumvec[GY * ND];             // per-split class-sum vectors (fp32 of bf16)
__device__ __nv_bfloat16 g_pred_bf[NB * ND];    // sign-folded pred (bf16)
__device__ __nv_bfloat16 g_emb_bf[NC * ND];     // class embeddings (bf16)

// ---------------- helpers -----------------------------------------------------
__device__ __forceinline__ uint32_t smem_u32(const void* p) {
    uint32_t r;
    asm("{ .reg .u64 t; cvta.to.shared.u64 t, %1; cvt.u32.u64 %0, t; }" : "=r"(r) : "l"(p));
    return r;
}
__device__ __forceinline__ void cp16(uint32_t dst, const void* src) {
    asm volatile("cp.async.cg.shared.global [%0], [%1], 16;" :: "r"(dst), "l"(src));
}
__device__ __forceinline__ void ldsm4(uint32_t& r0, uint32_t& r1, uint32_t& r2, uint32_t& r3,
                                      uint32_t a) {
    asm volatile("ldmatrix.sync.aligned.m8n8.x4.shared.b16 {%0,%1,%2,%3}, [%4];"
                 : "=r"(r0), "=r"(r1), "=r"(r2), "=r"(r3) : "r"(a));
}
__device__ __forceinline__ void mma16816(float* c, const uint32_t* a, uint32_t b0, uint32_t b1) {
    asm volatile(
        "mma.sync.aligned.m16n8k16.row.col.f32.bf16.bf16.f32 "
        "{%0,%1,%2,%3}, {%4,%5,%6,%7}, {%8,%9}, {%0,%1,%2,%3};"
        : "+f"(c[0]), "+f"(c[1]), "+f"(c[2]), "+f"(c[3])
        : "r"(a[0]), "r"(a[1]), "r"(a[2]), "r"(a[3]), "r"(b0), "r"(b1));
}
__device__ __forceinline__ float sqrt_approx(float x) {
    float r; asm("sqrt.approx.f32 %0, %1;" : "=f"(r) : "f"(x)); return r;
}
// packed f32x2 (compile-verified on this toolchain in an earlier round)
__device__ __forceinline__ ull ffma2(ull a, ull b, ull c) {
    ull d; asm("fma.rn.f32x2 %0, %1, %2, %3;" : "=l"(d) : "l"(a), "l"(b), "l"(c)); return d;
}
__device__ __forceinline__ ull fadd2(ull a, ull b) {
    ull d; asm("add.rn.f32x2 %0, %1, %2;" : "=l"(d) : "l"(a), "l"(b)); return d;
}
__device__ __forceinline__ ull pack2(float lo, float hi) {
    ull d; asm("mov.b64 %0, {%1, %2};" : "=l"(d) : "f"(lo), "f"(hi)); return d;
}
__device__ __forceinline__ float sum2(ull v) {
    float lo, hi; asm("mov.b64 {%0, %1}, %2;" : "=f"(lo), "=f"(hi) : "l"(v)); return lo + hi;
}
// packed sqrt of both halves with NaN-flush clamp (fmaxf(NaN,0)=0)
__device__ __forceinline__ ull sq2(ull q) {
    float a, b;
    asm("mov.b64 {%0, %1}, %2;" : "=f"(a), "=f"(b) : "l"(q));
    a = fmaxf(sqrt_approx(a), 0.0f);
    b = fmaxf(sqrt_approx(b), 0.0f);
    ull r; asm("mov.b64 %0, {%1, %2};" : "=l"(r) : "f"(a), "f"(b));
    return r;
}

// ---------------- k_pre: merged conversions + zero accums ---------------------
// blocks [0,PREB): pred -> bf16 sign-folded; blocks [PREB, PREB+2000): embs -> bf16.
__global__ void __launch_bounds__(256) k_pre(const float* __restrict__ pred,
                                             const float* __restrict__ embs,
                                             float* __restrict__ out) {
    int b   = blockIdx.x;
    int tid = threadIdx.x;
    if (b < PREB) {
        int i = b * 256 + tid;                         // < 131072
        float2 v = reinterpret_cast<const float2*>(pred)[i];
        int k = (i * 2) & 31;
        float a = (k == 0) ? v.x : -v.x;
        reinterpret_cast<__nv_bfloat162*>(g_pred_bf)[i] = __floats2bfloat162_rn(a, -v.y);
        if (i < NB) g_S[i] = 0.0f;
        if (i == 0) out[0] = 0.0f;
    } else {
        int i = (b - PREB) * 256 + tid;                // < 512000
        float2 v = reinterpret_cast<const float2*>(embs)[i];
        reinterpret_cast<__nv_bfloat162*>(g_emb_bf)[i] = __floats2bfloat162_rn(v.x, v.y);
    }
}

// ---------------- k_aux: class-sum vectors + target distances -----------------
__global__ void __launch_bounds__(256) k_aux(const float* __restrict__ pred,
                                             const int* __restrict__ tgt,
                                             const float* __restrict__ embs) {
    int b   = blockIdx.x;
    int tid = threadIdx.x;
    if (b < GY) {
        __shared__ float red[8][32];
        int dim = tid & 31;
        int ch  = tid >> 5;                    // 8 chunks of 80 classes
        const __nv_bfloat16* base = g_emb_bf + (size_t)b * CPS * ND;
        float acc = 0.0f;
#pragma unroll 4
        for (int c = ch * 80; c < ch * 80 + 80; c++)
            acc += __bfloat162float(base[c * ND + dim]);
        red[ch][dim] = acc;
        __syncthreads();                       // convergent within this block
        if (ch == 0) {
            float t = acc;
#pragma unroll
            for (int k = 1; k < 8; k++) t += red[k][dim];
            g_sumvec[b * ND + dim] = t;
        }
    } else {
        // warp-per-row gather: lane = dimension, no barriers in this branch
        int r    = ((b - GY) * 256 + tid) >> 5;     // row 0..8191
        int lane = tid & 31;
        int t = tgt[r];
        float p = pred[r * ND + lane];
        float e = __ldg(&embs[(size_t)t * ND + lane]);
        float term = (lane == 0) ? p * e : -p * e;
#pragma unroll
        for (int o = 16; o; o >>= 1) term += __shfl_xor_sync(0xffffffffu, term, o);
        if (lane == 0) g_D[r] = acoshf(fmaxf(term, Y_MIN));
    }
}

// ---------------- main: mma.sync GEMM + packed-f32x2 sqrt epilogue ------------
__global__ void __launch_bounds__(256) k_main() {
    __shared__ __align__(16) char sA[TM * RPAD];        // 10240 B
    __shared__ __align__(16) char sB[2][TN * RPAD];     // 2 x 10240 B
    __shared__ float s_ydot[TM];

    const int tid  = threadIdx.x;
    const int w    = tid >> 5;
    const int lane = tid & 31;

    const uint32_t a_s = smem_u32(sA);
    const uint32_t b_s = smem_u32(sB);

    const char* gA = reinterpret_cast<const char*>(g_pred_bf) + (size_t)blockIdx.x * TM * 64;
    const int cls_base = blockIdx.y * (TPC * TN);
    const char* gB0 = reinterpret_cast<const char*>(g_emb_bf) + (size_t)cls_base * 64;

    // ---- prologue: stage A and B tile 0 ----
#pragma unroll
    for (int i = 0; i < 2; i++) {
        int L = tid + i * 256;                 // 512 x 16B chunks each
        int r = L >> 2, c = L & 3;
        cp16(a_s + r * RPAD + c * 16, gA + r * 64 + c * 16);
        cp16(b_s + r * RPAD + c * 16, gB0 + r * 64 + c * 16);
    }
    asm volatile("cp.async.commit_group;" ::: "memory");
    asm volatile("cp.async.wait_group 0;" ::: "memory");
    __syncthreads();

    // ---- per-row Sum(y) via sumvec dot (warp-uniform guard, no barrier) ----
    if (tid < TM) {
        const float* sv = g_sumvec + blockIdx.y * ND;
        const __nv_bfloat162* ar = reinterpret_cast<const __nv_bfloat162*>(sA + tid * RPAD);
        float d = 0.0f;
#pragma unroll
        for (int k = 0; k < 16; k++) {
            float2 u = __bfloat1622float2(ar[k]);
            d = fmaf(u.x, sv[2 * k], d);
            d = fmaf(u.y, sv[2 * k + 1], d);
        }
        s_ydot[tid] = d;
    }

    // ---- A fragments (rows w*16 .. w*16+15, K=32) ----
    const int rA = (lane & 7) + ((lane >> 3) & 1) * 8;
    const int cA = (lane >> 4) & 1;
    uint32_t afrag[2][4];
    {
        uint32_t base = a_s + (w * 16 + rA) * RPAD + cA * 16;
        ldsm4(afrag[0][0], afrag[0][1], afrag[0][2], afrag[0][3], base);
        ldsm4(afrag[1][0], afrag[1][1], afrag[1][2], afrag[1][3], base + 32);
    }

    const int rB = (lane & 7) + ((lane >> 4) & 1) * 8;
    const int cB = (lane >> 3) & 1;

    // packed accumulators: a0/a1 -> row lane>>2 ; a2/a3 -> row (lane>>2)+8
    ull a0 = 0, a1 = 0, a2 = 0, a3 = 0;

    int buf = 0;
#pragma unroll 1
    for (int t = 0; t < TPC; t++) {
        if (t + 1 < TPC) {
            const char* gB = reinterpret_cast<const char*>(g_emb_bf)
                           + (size_t)(cls_base + (t + 1) * TN) * 64;
            uint32_t dst = b_s + (buf ^ 1) * BUFB;
#pragma unroll
            for (int i = 0; i < 2; i++) {
                int L = tid + i * 256;
                int r = L >> 2, c = L & 3;
                cp16(dst + r * RPAD + c * 16, gB + r * 64 + c * 16);
            }
            asm volatile("cp.async.commit_group;" ::: "memory");
            asm volatile("cp.async.wait_group 1;" ::: "memory");
        } else {
            asm volatile("cp.async.wait_group 0;" ::: "memory");
        }
        __syncthreads();

        const uint32_t bbase = b_s + buf * BUFB + rB * RPAD + cB * 16;

#pragma unroll
        for (int g = 0; g < TN / 16; g++) {          // 8 groups of 16 classes
            float cL[4] = {0.f, 0.f, 0.f, 0.f};
            float cH[4] = {0.f, 0.f, 0.f, 0.f};
#pragma unroll
            for (int ks = 0; ks < 2; ks++) {
                uint32_t bL0, bL1, bH0, bH1;
                ldsm4(bL0, bL1, bH0, bH1, bbase + g * (16 * RPAD) + ks * 32);
                mma16816(cL, afrag[ks], bL0, bL1);
                mma16816(cH, afrag[ks], bH0, bH1);
            }
            // packed epilogue: q = y*y-1 (FFMA2), sqrt+NaN-flush, accumulate (FADD2)
            ull pL01 = pack2(cL[0], cL[1]);
            ull pL23 = pack2(cL[2], cL[3]);
            ull pH01 = pack2(cH[0], cH[1]);
            ull pH23 = pack2(cH[2], cH[3]);
            a0 = fadd2(a0, sq2(ffma2(pL01, pL01, NEG1_2)));
            a1 = fadd2(a1, sq2(ffma2(pH01, pH01, NEG1_2)));
            a2 = fadd2(a2, sq2(ffma2(pL23, pL23, NEG1_2)));
            a3 = fadd2(a3, sq2(ffma2(pH23, pH23, NEG1_2)));
        }
        __syncthreads();     // all warps done with buf before it is overwritten
        buf ^= 1;
    }

    // reduce: row lane>>2 gets a0+a1 ; row (lane>>2)+8 gets a2+a3
    float rlo = sum2(fadd2(a0, a1));
    float rhi = sum2(fadd2(a2, a3));
#pragma unroll
    for (int o = 1; o <= 2; o <<= 1) {
        rlo += __shfl_xor_sync(0xffffffffu, rlo, o);
        rhi += __shfl_xor_sync(0xffffffffu, rhi, o);
    }
    if ((lane & 3) == 0) {
        int rloc = w * 16 + (lane >> 2);
        int rowbase = blockIdx.x * TM + rloc;
        atomicAdd(&g_S[rowbase],     s_ydot[rloc]     - rlo);   // Sum(y - sqrt(y^2-1))
        atomicAdd(&g_S[rowbase + 8], s_ydot[rloc + 8] - rhi);
    }
}

// ---------------- k_log: nll = log(S) + dist_target, mean ---------------------
__global__ void __launch_bounds__(256) k_log(float* __restrict__ out) {
    __shared__ float sm[8];
    int r = blockIdx.x * 256 + threadIdx.x;     // grid 32 -> r < 8192
    float nll = logf(g_S[r]) + g_D[r];
#pragma unroll
    for (int o = 16; o; o >>= 1) nll += __shfl_down_sync(0xffffffffu, nll, o);
    if ((threadIdx.x & 31) == 0) sm[threadIdx.x >> 5] = nll;
    __syncthreads();                            // convergent: all threads
    if (threadIdx.x == 0) {
        float s = 0.0f;
#pragma unroll
        for (int k = 0; k < 8; k++) s += sm[k];
        atomicAdd(out, s * (1.0f / NB));
    }
}

// ---------------- launch ------------------------------------------------------
extern "C" void kernel_launch(void* const* d_in, const int* in_sizes, int n_in,
                              void* d_out, int out_size) {
    const float* pred = (const float*)d_in[0];
    const int*   tgt  = (const int*)  d_in[1];
    const float* embs = (const float*)d_in[2];
    float* out = (float*)d_out;

    k_pre<<<PREB + (NC * ND / 2) / 256, 256>>>(pred, embs, out);
    k_aux<<<GY + NB * 32 / 256, 256>>>(pred, tgt, embs);
    k_main<<<dim3(GX, GY), 256>>>();
    k_log<<<NB / 256, 256>>>(out);
}